// round 4
// baseline (speedup 1.0000x reference)
#include <cuda_runtime.h>

// StepRelu: y = 0 for x<=0; ((ceil(x/theta)-1)*theta) for 0<x<=theta*steps; x otherwise.
// theta = 0.1, steps = 16 -> upper = 1.6.
// Pure elementwise, HBM-bound. float4 vectorized, one pass.

__device__ __forceinline__ float step_relu(float x) {
    const float theta     = 0.1f;
    const float inv_theta = 10.0f;   // 1/theta
    const float upper     = 1.6f;    // theta * 16
    float binned = (ceilf(x * inv_theta) - 1.0f) * theta;
    float y = (x <= upper) ? binned : x;
    return (x <= 0.0f) ? 0.0f : y;
}

__global__ void __launch_bounds__(256) step_relu_kernel_v4(
    const float4* __restrict__ in, float4* __restrict__ out, int n4)
{
    int i = blockIdx.x * blockDim.x + threadIdx.x;
    if (i < n4) {
        float4 v = in[i];
        float4 r;
        r.x = step_relu(v.x);
        r.y = step_relu(v.y);
        r.z = step_relu(v.z);
        r.w = step_relu(v.w);
        out[i] = r;
    }
}

__global__ void step_relu_kernel_tail(
    const float* __restrict__ in, float* __restrict__ out, int start, int n)
{
    int i = start + blockIdx.x * blockDim.x + threadIdx.x;
    if (i < n) out[i] = step_relu(in[i]);
}

extern "C" void kernel_launch(void* const* d_in, const int* in_sizes, int n_in,
                              void* d_out, int out_size)
{
    const float* x = (const float*)d_in[0];
    float* y = (float*)d_out;
    int n = in_sizes[0];

    int n4 = n / 4;
    if (n4 > 0) {
        int threads = 256;
        int blocks = (n4 + threads - 1) / threads;
        step_relu_kernel_v4<<<blocks, threads>>>(
            (const float4*)x, (float4*)y, n4);
    }
    int rem = n - n4 * 4;
    if (rem > 0) {
        step_relu_kernel_tail<<<1, 256>>>(x, y, n4 * 4, n);
    }
}

// round 5
// speedup vs baseline: 1.1138x; 1.1138x over previous
#include <cuda_runtime.h>

// StepRelu: y = 0 for x<=0; ((ceil(x/theta)-1)*theta) for 0<x<=theta*steps; x otherwise.
// theta = 0.1, steps = 16 -> upper = 1.6.
// R5: 4x float4 per thread, loads front-batched for MLP (~24KB in flight/SM),
// streaming cache hints (read-once / write-once working set).

#define VEC 4  // float4s per thread

__device__ __forceinline__ float step_relu(float x) {
    const float theta     = 0.1f;
    const float inv_theta = 10.0f;
    const float upper     = 1.6f;
    float binned = (ceilf(x * inv_theta) - 1.0f) * theta;
    float y = (x <= upper) ? binned : x;
    return (x <= 0.0f) ? 0.0f : y;
}

__device__ __forceinline__ float4 step_relu4(float4 v) {
    float4 r;
    r.x = step_relu(v.x);
    r.y = step_relu(v.y);
    r.z = step_relu(v.z);
    r.w = step_relu(v.w);
    return r;
}

// Fast path: n4 divisible by blockDim*VEC, no bounds checks.
__global__ void __launch_bounds__(256) step_relu_v4x4_exact(
    const float4* __restrict__ in, float4* __restrict__ out)
{
    int base = blockIdx.x * (256 * VEC) + threadIdx.x;

    float4 v[VEC];
#pragma unroll
    for (int k = 0; k < VEC; k++)
        v[k] = __ldcs(in + base + k * 256);   // independent, front-batched

#pragma unroll
    for (int k = 0; k < VEC; k++)
        __stcs(out + base + k * 256, step_relu4(v[k]));
}

// Generic guarded path (covers any n4 remainder region).
__global__ void __launch_bounds__(256) step_relu_v4_guard(
    const float4* __restrict__ in, float4* __restrict__ out, int start, int n4)
{
    int i = start + blockIdx.x * blockDim.x + threadIdx.x;
    if (i < n4) __stcs(out + i, step_relu4(__ldcs(in + i)));
}

// Scalar tail for n % 4 != 0.
__global__ void step_relu_tail(
    const float* __restrict__ in, float* __restrict__ out, int start, int n)
{
    int i = start + blockIdx.x * blockDim.x + threadIdx.x;
    if (i < n) out[i] = step_relu(in[i]);
}

extern "C" void kernel_launch(void* const* d_in, const int* in_sizes, int n_in,
                              void* d_out, int out_size)
{
    const float* x = (const float*)d_in[0];
    float* y = (float*)d_out;
    int n = in_sizes[0];

    int n4 = n / 4;
    const int per_block = 256 * VEC;          // 1024 float4s per block
    int exact_blocks = n4 / per_block;

    if (exact_blocks > 0) {
        step_relu_v4x4_exact<<<exact_blocks, 256>>>(
            (const float4*)x, (float4*)y);
    }
    int done4 = exact_blocks * per_block;
    int rem4 = n4 - done4;
    if (rem4 > 0) {
        int blocks = (rem4 + 255) / 256;
        step_relu_v4_guard<<<blocks, 256>>>(
            (const float4*)x, (float4*)y, done4, n4);
    }
    int rem = n - n4 * 4;
    if (rem > 0) {
        step_relu_tail<<<1, 256>>>(x, y, n4 * 4, n);
    }
}